// round 4
// baseline (speedup 1.0000x reference)
#include <cuda_runtime.h>
#include <cstdint>

// GeometricStrideUnpool fused kernel:
//   out[m, :] = g(m) @ proj + bias,  m = b*8192 + l*4 + ki
// g(m) (3072 wide) generated on the fly in smem from x and W; GEMM via
// mma.sync.m16n8k8 TF32 (rna-rounded both operands), cp.async double-buffered.

#define THREADS 512
#define NCHUNK  96            // K=3072 / BK=32

// smem layout (floats)
#define XS_OFF 0              // 33 * 512 src vectors
#define WS_OFF 16896          // 4 * 512 W rows
#define G_OFF  18944          // 2 buffers of 128*36 (g tile, tf32 bits)
#define G_SZ   4608
#define P_OFF  28160          // 2 buffers of 32*136 (proj tile, raw fp32)
#define P_SZ   4352
#define SMEM_FLOATS 36864
#define SMEM_BYTES  (SMEM_FLOATS * 4)

__device__ __forceinline__ uint32_t f2tf32(float f) {
    uint32_t r;
    asm("cvt.rna.tf32.f32 %0, %1;" : "=r"(r) : "f"(f));
    return r;
}

__device__ __forceinline__ void cp16(void* dst, const void* src) {
    uint32_t d = (uint32_t)__cvta_generic_to_shared(dst);
    asm volatile("cp.async.cg.shared.global [%0], [%1], 16;" :: "r"(d), "l"(src));
}

__device__ __forceinline__ void mma_tf32(float* c, const uint32_t* a, uint32_t b0, uint32_t b1) {
    asm volatile(
        "mma.sync.aligned.m16n8k8.row.col.f32.tf32.tf32.f32 "
        "{%0,%1,%2,%3}, {%4,%5,%6,%7}, {%8,%9}, {%0,%1,%2,%3};"
        : "+f"(c[0]), "+f"(c[1]), "+f"(c[2]), "+f"(c[3])
        : "r"(a[0]), "r"(a[1]), "r"(a[2]), "r"(a[3]), "r"(b0), "r"(b1));
}

__global__ void __launch_bounds__(THREADS, 1)
gsu_fused_kernel(const float* __restrict__ x, const float* __restrict__ W,
                 const float* __restrict__ proj, const float* __restrict__ bias,
                 float* __restrict__ out)
{
    extern __shared__ float sm[];
    float* xs = sm + XS_OFF;
    float* ws = sm + WS_OFF;

    const int t  = threadIdx.x;
    const int m0 = blockIdx.x * 128;   // 256 m-tiles; one batch spans 64 tiles
    const int n0 = blockIdx.y * 128;   // 4 n-tiles
    const int b  = m0 >> 13;           // 8192 rows per batch
    const int l0 = (m0 & 8191) >> 2;   // first l covered by this tile

    // ---------------- prologue: stage xs (33 vectors), ws, proj chunk 0 ----------------
    const float* xbase = x + (size_t)b * (2048 * 512);
    for (int idx = t; idx < 33 * 128; idx += THREADS) {
        int v = idx >> 7, c4 = idx & 127;
        int l = l0 - 1 + v;                 // v=0 is the "previous" vector
        float* dst = xs + v * 512 + c4 * 4;
        if (l >= 0) cp16(dst, xbase + (size_t)l * 512 + c4 * 4);
        else        *(float4*)dst = make_float4(0.f, 0.f, 0.f, 0.f);  // zero pad at l=-1
    }
    cp16(ws + t * 4, W + t * 4);            // 512 threads * 4 floats = 2048 = 4*512
    #pragma unroll
    for (int q = 0; q < 2; q++) {           // proj chunk 0: 32 rows x 128 cols
        int idx = t + THREADS * q;
        int kk = idx >> 5, c4 = idx & 31;
        cp16(sm + P_OFF + kk * 136 + c4 * 4, proj + (size_t)kk * 512 + n0 + c4 * 4);
    }
    asm volatile("cp.async.commit_group;");
    asm volatile("cp.async.wait_group 0;");
    __syncthreads();

    // ---------------- g-tile generator ----------------
    // Each warp owns one m-row per step (m uniform across lanes, kk = lane):
    // all xs/ws shared loads are 32 consecutive words -> conflict-free.
    const int kk_ = t & 31;
    const int mrb = t >> 5;    // 0..15

    auto buildG = [&](int k0, float* gbuf) {
        const int  bi      = k0 >> 9;                      // component block 0..5
        const int  s       = (bi < 2) ? 1 : (bi < 4 ? 2 : 4);
        const bool is_silu = (bi & 1);
        const int  j       = (k0 & 511) + kk_;             // stays inside the 512-block
        const int  jm      = (j - s) & 511;
        uint32_t*  gu      = (uint32_t*)gbuf;
        #pragma unroll
        for (int q = 0; q < 8; q++) {
            int m   = mrb + 16 * q;                        // 0..127
            int ki  = m & 3;
            int vec = (m >> 2) + (ki == 3 ? 1 : 0);        // src vector index
            float sv_j  = xs[vec * 512 + j];
            float sv_jm = xs[vec * 512 + jm];
            float w_j   = ws[ki * 512 + j];
            float w_jm  = ws[ki * 512 + jm];
            float swv = sv_j * w_jm;                       // src * roll(W, s)
            float gv;
            if (is_silu) gv = swv * (1.0f / (1.0f + __expf(-swv)));
            else         gv = swv - w_j * sv_jm;           // sw - W * roll(src, s)
            gu[m * 36 + kk_] = f2tf32(gv);                 // round once at store
        }
    };

    buildG(0, sm + G_OFF);
    __syncthreads();

    // ---------------- main loop: double-buffered K over 96 chunks ----------------
    float acc[2][4][4];
    #pragma unroll
    for (int i = 0; i < 2; i++)
        #pragma unroll
        for (int jv = 0; jv < 4; jv++)
            #pragma unroll
            for (int r = 0; r < 4; r++) acc[i][jv][r] = 0.f;

    const int warp = t >> 5, lane = t & 31;
    const int wm = warp >> 2, wn = warp & 3;      // 4x4 warp grid, 32x32 warp tiles
    const int gid = lane >> 2, tig = lane & 3;

    for (int it = 0; it < NCHUNK; it++) {
        const int cur = it & 1, nxt = cur ^ 1;
        if (it + 1 < NCHUNK) {
            const int k0n = (it + 1) * 32;
            #pragma unroll
            for (int q = 0; q < 2; q++) {
                int idx = t + THREADS * q;
                int kk = idx >> 5, c4 = idx & 31;
                cp16(sm + P_OFF + nxt * P_SZ + kk * 136 + c4 * 4,
                     proj + (size_t)(k0n + kk) * 512 + n0 + c4 * 4);
            }
            asm volatile("cp.async.commit_group;");
            buildG(k0n, sm + G_OFF + nxt * G_SZ);
        }

        const uint32_t* gu = (const uint32_t*)(sm + G_OFF + cur * G_SZ);
        const float*    pf = sm + P_OFF + cur * P_SZ;

        #pragma unroll
        for (int ks = 0; ks < 4; ks++) {
            uint32_t a[2][4];
            #pragma unroll
            for (int mi = 0; mi < 2; mi++) {
                int r = wm * 32 + mi * 16 + gid;
                int c = ks * 8 + tig;
                a[mi][0] = gu[r * 36 + c];           // (row, col)
                a[mi][1] = gu[(r + 8) * 36 + c];     // (row+8, col)
                a[mi][2] = gu[r * 36 + c + 4];       // (row, col+4)
                a[mi][3] = gu[(r + 8) * 36 + c + 4]; // (row+8, col+4)
            }
            #pragma unroll
            for (int nb = 0; nb < 4; nb++) {
                int cc = wn * 32 + nb * 8 + gid;
                uint32_t b0 = f2tf32(pf[(ks * 8 + tig) * 136 + cc]);
                uint32_t b1 = f2tf32(pf[(ks * 8 + tig + 4) * 136 + cc]);
                mma_tf32(acc[0][nb], a[0], b0, b1);
                mma_tf32(acc[1][nb], a[1], b0, b1);
            }
        }

        asm volatile("cp.async.wait_group 0;");
        __syncthreads();
    }

    // ---------------- epilogue: acc + bias -> out ----------------
    #pragma unroll
    for (int mi = 0; mi < 2; mi++) {
        #pragma unroll
        for (int nb = 0; nb < 4; nb++) {
            int r = m0 + wm * 32 + mi * 16 + gid;
            int c = n0 + wn * 32 + nb * 8 + tig * 2;
            float b0 = __ldg(bias + c);
            float b1 = __ldg(bias + c + 1);
            *(float2*)(out + (size_t)r * 512 + c) =
                make_float2(acc[mi][nb][0] + b0, acc[mi][nb][1] + b1);
            *(float2*)(out + (size_t)(r + 8) * 512 + c) =
                make_float2(acc[mi][nb][2] + b0, acc[mi][nb][3] + b1);
        }
    }
}

extern "C" void kernel_launch(void* const* d_in, const int* in_sizes, int n_in,
                              void* d_out, int out_size)
{
    const float* x    = (const float*)d_in[0];  // (4,1,2048,512)
    const float* W    = (const float*)d_in[1];  // (4,512)
    const float* proj = (const float*)d_in[2];  // (3072,512)
    const float* bias = (const float*)d_in[3];  // (512,)
    float* out = (float*)d_out;                 // (4,1,8192,512)

    cudaFuncSetAttribute(gsu_fused_kernel,
                         cudaFuncAttributeMaxDynamicSharedMemorySize, SMEM_BYTES);
    dim3 grid(256, 4);
    gsu_fused_kernel<<<grid, THREADS, SMEM_BYTES>>>(x, W, proj, bias, out);
}

// round 5
// speedup vs baseline: 1.2454x; 1.2454x over previous
#include <cuda_runtime.h>
#include <cstdint>

// GeometricStrideUnpool, round 2:
//  out[m,:] = v(m) @ M_ki  +  silu_g(m) @ P_silu  + bias
// Linear (comp1) part folded into precomputed per-ki 512x512 matrices (K=512).
// Silu part stays a fused K=1536 GEMM. Both via mma.sync m16n8k8 TF32.
// B operands precomputed in gmem: transposed, tf32-rounded, k-permuted within
// 8-groups so (k, k+4) are adjacent -> single conflict-free LDS.64 per fragment.

#define THREADS 512

// ---- smem layout (floats) ----
#define XS_OFF 0            // 33 x 512 staged src vectors
#define WS_OFF 16896        // 4 x 512 W
#define GL_OFF 18944        // phase L A tiles: 2 x 128 x 24
#define GL_SZ  3072
#define PL_OFF 25088        // phase L B tiles: 2 x (4 x 128 x 24)
#define PL_SZ  12288
#define GS_OFF 18944        // phase S A tiles: 2 x 128 x 40 (overlaps GL, phases disjoint)
#define GS_SZ  5120
#define PS_OFF 29184        // phase S B tiles: 2 x 128 x 40
#define PS_SZ  5120
#define SMEM_FLOATS 49664
#define SMEM_BYTES  (SMEM_FLOATS * 4)

// gmem scratch (written by prep kernels each launch)
__device__ float g_Mt[4u * 512 * 512];     // [ki][n][k'] tf32 bits, k' permuted
__device__ float g_PSt[512u * 1536];       // [n][k'] tf32 bits of silu proj rows

__device__ __host__ __forceinline__ int kperm8(int k) {
    // within-8 permutation: slot = 2*(k&3) + ((k>>2)&1); pairs (k,k+4) adjacent
    return (k & ~7) | (((k & 3) << 1) | ((k >> 2) & 1));
}

__device__ __forceinline__ uint32_t f2tf32(float f) {
    uint32_t r;
    asm("cvt.rna.tf32.f32 %0, %1;" : "=r"(r) : "f"(f));
    return r;
}

__device__ __forceinline__ void cp16(void* dst, const void* src) {
    uint32_t d = (uint32_t)__cvta_generic_to_shared(dst);
    asm volatile("cp.async.cg.shared.global [%0], [%1], 16;" :: "r"(d), "l"(src));
}

__device__ __forceinline__ void mma_tf32(float* c, const uint32_t* a, uint32_t b0, uint32_t b1) {
    asm volatile(
        "mma.sync.aligned.m16n8k8.row.col.f32.tf32.tf32.f32 "
        "{%0,%1,%2,%3}, {%4,%5,%6,%7}, {%8,%9}, {%0,%1,%2,%3};"
        : "+f"(c[0]), "+f"(c[1]), "+f"(c[2]), "+f"(c[3])
        : "r"(a[0]), "r"(a[1]), "r"(a[2]), "r"(a[3]), "r"(b0), "r"(b1));
}

// ---------------- prep kernel 1: M_ki[c,d] fold, transposed + permuted + tf32 ----------------
__global__ void prep_M(const float* __restrict__ proj, const float* __restrict__ W) {
    __shared__ float tile[32][33];
    const int ki = blockIdx.z;
    const int k0 = blockIdx.x * 32, n0 = blockIdx.y * 32;
    const int tx = threadIdx.x, ty = threadIdx.y;      // (32, 8)
    #pragma unroll
    for (int q = 0; q < 4; q++) {
        int kl = ty * 4 + q, k = k0 + kl, n = n0 + tx;
        float acc = 0.f;
        #pragma unroll
        for (int si = 0; si < 3; si++) {
            int s = 1 << si;
            int base = si * 1024;                      // comp1 blocks at rows 0,1024,2048
            float p1 = proj[(size_t)(base + k) * 512 + n];
            float p2 = proj[(size_t)(base + ((k + s) & 511)) * 512 + n];
            float w1 = __ldg(W + ki * 512 + ((k - s) & 511));
            float w2 = __ldg(W + ki * 512 + ((k + s) & 511));
            acc += w1 * p1 - w2 * p2;
        }
        tile[kl][tx] = acc;
    }
    __syncthreads();
    #pragma unroll
    for (int q = 0; q < 4; q++) {
        int nl = ty * 4 + q, n = n0 + nl;
        int k = k0 + tx;
        ((uint32_t*)g_Mt)[(((size_t)ki * 512 + n) << 9) + kperm8(k)] = f2tf32(tile[tx][nl]);
    }
}

// ---------------- prep kernel 2: silu proj rows, transposed + permuted + tf32 ----------------
__global__ void prep_PS(const float* __restrict__ proj) {
    __shared__ float tile[32][33];
    const int k0 = blockIdx.x * 32, n0 = blockIdx.y * 32;   // k over 0..1535
    const int tx = threadIdx.x, ty = threadIdx.y;
    const int blk = k0 >> 9;                                // silu block 0..2
    const int srow0 = 512 + blk * 1024;
    #pragma unroll
    for (int q = 0; q < 4; q++) {
        int kl = ty * 4 + q, k = k0 + kl;
        tile[kl][tx] = proj[(size_t)(srow0 + (k & 511)) * 512 + n0 + tx];
    }
    __syncthreads();
    #pragma unroll
    for (int q = 0; q < 4; q++) {
        int nl = ty * 4 + q, n = n0 + nl;
        int k = k0 + tx;
        ((uint32_t*)g_PSt)[(size_t)n * 1536 + kperm8(k)] = f2tf32(tile[tx][nl]);
    }
}

// ---------------- main fused kernel ----------------
__global__ void __launch_bounds__(THREADS, 1)
gsu2_kernel(const float* __restrict__ x, const float* __restrict__ W,
            const float* __restrict__ bias, float* __restrict__ out)
{
    extern __shared__ float sm[];
    float* xs = sm + XS_OFF;
    float* ws = sm + WS_OFF;

    const int t    = threadIdx.x;
    const int warp = t >> 5, lane = t & 31;
    const int b    = blockIdx.x >> 6;
    const int l0   = (blockIdx.x & 63) * 32;
    const int n0   = blockIdx.y * 128;

    const int wm = warp >> 2, wn = warp & 3;   // 4x4 warp grid; warp-row wm <=> ki
    const int gid = lane >> 2, tig = lane & 3;

    // ---------- prologue: stage xs (33 vectors), ws, PL chunk 0 ----------
    const float* xbase = x + (size_t)b * (2048 * 512);
    for (int idx = t; idx < 33 * 128; idx += THREADS) {
        int v = idx >> 7, c4 = idx & 127;
        int l = l0 - 1 + v;
        float* dst = xs + v * 512 + c4 * 4;
        if (l >= 0) cp16(dst, xbase + (size_t)l * 512 + c4 * 4);
        else        *(float4*)dst = make_float4(0.f, 0.f, 0.f, 0.f);
    }
    cp16(ws + t * 4, W + t * 4);

    auto loadPL = [&](int k0c, float* dst) {   // 4ki x 128n x 16k
        #pragma unroll
        for (int q = 0; q < 4; q++) {
            int idx = t + THREADS * q;         // 0..2047
            int ki = idx >> 9, n = (idx >> 2) & 127, c4 = idx & 3;
            cp16(dst + ki * 3072 + n * 24 + c4 * 4,
                 g_Mt + (((size_t)ki * 512 + n0 + n) << 9) + k0c + c4 * 4);
        }
    };
    auto loadPS = [&](int k0c, float* dst) {   // 128n x 32k
        #pragma unroll
        for (int q = 0; q < 2; q++) {
            int idx = t + THREADS * q;         // 0..1023
            int n = idx >> 3, c4 = idx & 7;
            cp16(dst + n * 40 + c4 * 4,
                 g_PSt + (size_t)(n0 + n) * 1536 + k0c + c4 * 4);
        }
    };

    loadPL(0, sm + PL_OFF);
    asm volatile("cp.async.commit_group;");
    asm volatile("cp.async.wait_group 0;");
    __syncthreads();

    // ---------- g builders ----------
    // linear A: g[r, k] = tf32(v(r)[k0+k]), 128 x 16 tile, stride 24, permuted cols
    const int half = lane >> 4, cl = lane & 15;
    auto buildLin = [&](int k0c, float* gbuf) {
        uint32_t* gu = (uint32_t*)gbuf;
        #pragma unroll
        for (int q = 0; q < 4; q++) {
            int r  = (warp << 1) + (q << 5) + half;   // 0..127 each once
            int ki = r >> 5, li = r & 31;
            int vec = li + (ki == 3 ? 1 : 0);
            float v = xs[vec * 512 + k0c + cl];
            gu[r * 24 + kperm8(cl)] = f2tf32(v);
        }
    };
    // silu A: g[r, k] = tf32(silu(v[j] * W[ki][(j-s)&511])), 128 x 32 tile, stride 40
    auto buildSilu = [&](int jb, int s, float* gbuf) {
        uint32_t* gu = (uint32_t*)gbuf;
        const int j  = jb + lane;
        #pragma unroll
        for (int q = 0; q < 8; q++) {
            int m  = warp + 16 * q;
            int ki = m >> 5, li = m & 31;
            int vec = li + (ki == 3 ? 1 : 0);
            int jm  = (j - s) & 511;
            float sw = xs[vec * 512 + j] * ws[ki * 512 + jm];
            float gv = sw * (1.0f / (1.0f + __expf(-sw)));
            gu[m * 40 + kperm8(lane)] = f2tf32(gv);
        }
    };

    float acc[2][4][4];
    #pragma unroll
    for (int i = 0; i < 2; i++)
        #pragma unroll
        for (int jv = 0; jv < 4; jv++)
            #pragma unroll
            for (int r = 0; r < 4; r++) acc[i][jv][r] = 0.f;

    // ================= Phase L: K=512, BK=16, 32 chunks =================
    buildLin(0, sm + GL_OFF);
    __syncthreads();

    for (int it = 0; it < 32; it++) {
        const int cur = it & 1, nxt = cur ^ 1;
        if (it + 1 < 32) {
            loadPL((it + 1) * 16, sm + PL_OFF + nxt * PL_SZ);
            asm volatile("cp.async.commit_group;");
            buildLin((it + 1) * 16, sm + GL_OFF + nxt * GL_SZ);
        }
        const uint32_t* gu = (const uint32_t*)(sm + GL_OFF + cur * GL_SZ);
        const uint32_t* pu = (const uint32_t*)(sm + PL_OFF + cur * PL_SZ) + wm * 3072;

        #pragma unroll
        for (int ks = 0; ks < 2; ks++) {
            uint32_t a[2][4];
            #pragma unroll
            for (int mi = 0; mi < 2; mi++) {
                int r = wm * 32 + mi * 16 + gid;
                uint2 lo = *(const uint2*)(gu + r * 24 + 8 * ks + 2 * tig);
                uint2 hi = *(const uint2*)(gu + (r + 8) * 24 + 8 * ks + 2 * tig);
                a[mi][0] = lo.x; a[mi][1] = hi.x; a[mi][2] = lo.y; a[mi][3] = hi.y;
            }
            #pragma unroll
            for (int nb = 0; nb < 4; nb++) {
                int cc = wn * 32 + nb * 8 + gid;
                uint2 bb = *(const uint2*)(pu + cc * 24 + 8 * ks + 2 * tig);
                mma_tf32(acc[0][nb], a[0], bb.x, bb.y);
                mma_tf32(acc[1][nb], a[1], bb.x, bb.y);
            }
        }
        asm volatile("cp.async.wait_group 0;");
        __syncthreads();
    }

    // ================= Phase S: K=1536, BK=32, 48 chunks =================
    loadPS(0, sm + PS_OFF);
    asm volatile("cp.async.commit_group;");
    buildSilu(0, 1, sm + GS_OFF);
    asm volatile("cp.async.wait_group 0;");
    __syncthreads();

    for (int it = 0; it < 48; it++) {
        const int cur = it & 1, nxt = cur ^ 1;
        if (it + 1 < 48) {
            const int itn = it + 1;
            loadPS(itn * 32, sm + PS_OFF + nxt * PS_SZ);
            asm volatile("cp.async.commit_group;");
            buildSilu((itn & 15) * 32, 1 << (itn >> 4), sm + GS_OFF + nxt * GS_SZ);
        }
        const uint32_t* gu = (const uint32_t*)(sm + GS_OFF + cur * GS_SZ);
        const uint32_t* pu = (const uint32_t*)(sm + PS_OFF + cur * PS_SZ);

        #pragma unroll
        for (int ks = 0; ks < 4; ks++) {
            uint32_t a[2][4];
            #pragma unroll
            for (int mi = 0; mi < 2; mi++) {
                int r = wm * 32 + mi * 16 + gid;
                uint2 lo = *(const uint2*)(gu + r * 40 + 8 * ks + 2 * tig);
                uint2 hi = *(const uint2*)(gu + (r + 8) * 40 + 8 * ks + 2 * tig);
                a[mi][0] = lo.x; a[mi][1] = hi.x; a[mi][2] = lo.y; a[mi][3] = hi.y;
            }
            #pragma unroll
            for (int nb = 0; nb < 4; nb++) {
                int cc = wn * 32 + nb * 8 + gid;
                uint2 bb = *(const uint2*)(pu + cc * 40 + 8 * ks + 2 * tig);
                mma_tf32(acc[0][nb], a[0], bb.x, bb.y);
                mma_tf32(acc[1][nb], a[1], bb.x, bb.y);
            }
        }
        asm volatile("cp.async.wait_group 0;");
        __syncthreads();
    }

    // ---------- epilogue: permuted rows -> out ----------
    #pragma unroll
    for (int mi = 0; mi < 2; mi++) {
        int rloc = mi * 16 + gid;                       // 0..23 within ki group
        size_t row1 = (size_t)b * 8192 + (size_t)(l0 + rloc) * 4 + wm;
        size_t row2 = (size_t)b * 8192 + (size_t)(l0 + rloc + 8) * 4 + wm;
        #pragma unroll
        for (int nb = 0; nb < 4; nb++) {
            int c = n0 + wn * 32 + nb * 8 + tig * 2;
            float b0 = __ldg(bias + c);
            float b1 = __ldg(bias + c + 1);
            *(float2*)(out + row1 * 512 + c) =
                make_float2(acc[mi][nb][0] + b0, acc[mi][nb][1] + b1);
            *(float2*)(out + row2 * 512 + c) =
                make_float2(acc[mi][nb][2] + b0, acc[mi][nb][3] + b1);
        }
    }
}

extern "C" void kernel_launch(void* const* d_in, const int* in_sizes, int n_in,
                              void* d_out, int out_size)
{
    const float* x    = (const float*)d_in[0];  // (4,1,2048,512)
    const float* W    = (const float*)d_in[1];  // (4,512)
    const float* proj = (const float*)d_in[2];  // (3072,512)
    const float* bias = (const float*)d_in[3];  // (512,)
    float* out = (float*)d_out;                 // (4,1,8192,512)

    prep_M <<<dim3(16, 16, 4), dim3(32, 8)>>>(proj, W);
    prep_PS<<<dim3(48, 16),    dim3(32, 8)>>>(proj);

    cudaFuncSetAttribute(gsu2_kernel,
                         cudaFuncAttributeMaxDynamicSharedMemorySize, SMEM_BYTES);
    dim3 grid(256, 4);
    gsu2_kernel<<<grid, THREADS, SMEM_BYTES>>>(x, W, bias, out);
}

// round 6
// speedup vs baseline: 1.4296x; 1.1479x over previous
#include <cuda_runtime.h>
#include <cstdint>

// GeometricStrideUnpool, round 3: fixed-ki CTAs, unified 64-chunk K loop
// (interleaved lin/s1/s2/s4 per 32-col group), 3-stage cp.async pipeline,
// register-prefetched x for silu builds, precomputed tf32/permuted operands.

#define THREADS 512
#define TILE    5120          // 128 rows x 40 floats
// smem layout (floats)
#define WS_OFF  0             // 512: W[ki] row
#define GL_OFF  512           // 1 x TILE: linear A tiles (cp.async direct)
#define GS_OFF  5632          // 2 x TILE: silu A tiles
#define PB_OFF  15872         // 3 x TILE: B tiles
#define SMEM_FLOATS 31232
#define SMEM_BYTES  (SMEM_FLOATS * 4)

// gmem scratch written by prep kernels every launch
__device__ float g_Mt [4u * 512 * 512];    // [ki][n][k'] folded linear B, tf32, permuted
__device__ float g_PSt[512u * 1536];       // [n][si*512 + k'] silu proj B, tf32, permuted
__device__ float g_Xt [4u * 2048 * 512];   // [b][l][k'] x, tf32, permuted

__device__ __host__ __forceinline__ int kperm8(int k) {
    return (k & ~7) | (((k & 3) << 1) | ((k >> 2) & 1));   // (k,k+4) adjacent
}

__device__ __forceinline__ uint32_t f2tf32(float f) {
    uint32_t r;
    asm("cvt.rna.tf32.f32 %0, %1;" : "=r"(r) : "f"(f));
    return r;
}

__device__ __forceinline__ void cp16(void* dst, const void* src) {
    uint32_t d = (uint32_t)__cvta_generic_to_shared(dst);
    asm volatile("cp.async.cg.shared.global [%0], [%1], 16;" :: "r"(d), "l"(src));
}

__device__ __forceinline__ void mma_tf32(float* c, const uint32_t* a, uint32_t b0, uint32_t b1) {
    asm volatile(
        "mma.sync.aligned.m16n8k8.row.col.f32.tf32.tf32.f32 "
        "{%0,%1,%2,%3}, {%4,%5,%6,%7}, {%8,%9}, {%0,%1,%2,%3};"
        : "+f"(c[0]), "+f"(c[1]), "+f"(c[2]), "+f"(c[3])
        : "r"(a[0]), "r"(a[1]), "r"(a[2]), "r"(a[3]), "r"(b0), "r"(b1));
}

// ---------------- prep 1: fold linear part into M_ki, transpose+perm+tf32 ----------------
__global__ void prep_M(const float* __restrict__ proj, const float* __restrict__ W) {
    __shared__ float tile[32][33];
    const int ki = blockIdx.z;
    const int k0 = blockIdx.x * 32, n0 = blockIdx.y * 32;
    const int tx = threadIdx.x, ty = threadIdx.y;
    #pragma unroll
    for (int q = 0; q < 4; q++) {
        int kl = ty * 4 + q, k = k0 + kl, n = n0 + tx;
        float acc = 0.f;
        #pragma unroll
        for (int si = 0; si < 3; si++) {
            int s = 1 << si;
            int base = si * 1024;
            float p1 = proj[(size_t)(base + k) * 512 + n];
            float p2 = proj[(size_t)(base + ((k + s) & 511)) * 512 + n];
            float w1 = __ldg(W + ki * 512 + ((k - s) & 511));
            float w2 = __ldg(W + ki * 512 + ((k + s) & 511));
            acc += w1 * p1 - w2 * p2;
        }
        tile[kl][tx] = acc;
    }
    __syncthreads();
    #pragma unroll
    for (int q = 0; q < 4; q++) {
        int nl = ty * 4 + q, n = n0 + nl;
        int k = k0 + tx;
        ((uint32_t*)g_Mt)[(((size_t)ki * 512 + n) << 9) + kperm8(k)] = f2tf32(tile[tx][nl]);
    }
}

// ---------------- prep 2: silu proj rows, transpose+perm+tf32 ----------------
__global__ void prep_PS(const float* __restrict__ proj) {
    __shared__ float tile[32][33];
    const int k0 = blockIdx.x * 32, n0 = blockIdx.y * 32;
    const int tx = threadIdx.x, ty = threadIdx.y;
    const int srow0 = 512 + (k0 >> 9) * 1024;
    #pragma unroll
    for (int q = 0; q < 4; q++) {
        int kl = ty * 4 + q, k = k0 + kl;
        tile[kl][tx] = proj[(size_t)(srow0 + (k & 511)) * 512 + n0 + tx];
    }
    __syncthreads();
    #pragma unroll
    for (int q = 0; q < 4; q++) {
        int nl = ty * 4 + q, n = n0 + nl;
        int k = k0 + tx;
        ((uint32_t*)g_PSt)[(size_t)n * 1536 + kperm8(k)] = f2tf32(tile[tx][nl]);
    }
}

// ---------------- prep 3: x -> tf32 + permuted (for linear A cp.async) ----------------
__global__ void prep_X(const float* __restrict__ x) {
    size_t i = (size_t)blockIdx.x * 256 + threadIdx.x;   // float4 index, 1M total
    float4 v = ((const float4*)x)[i];
    uint32_t* dst = (uint32_t*)g_Xt + ((i >> 7) << 9);
    int k = (int)(i & 127) * 4;
    int base = k & ~7, odd = (k >> 2) & 1;
    dst[base + odd + 0] = f2tf32(v.x);
    dst[base + odd + 2] = f2tf32(v.y);
    dst[base + odd + 4] = f2tf32(v.z);
    dst[base + odd + 6] = f2tf32(v.w);
}

// ---------------- main fused kernel ----------------
__global__ void __launch_bounds__(THREADS, 1)
gsu3_kernel(const float* __restrict__ x, const float* __restrict__ W,
            const float* __restrict__ bias, float* __restrict__ out)
{
    extern __shared__ float sm[];
    float* ws = sm + WS_OFF;

    const int t = threadIdx.x, warp = t >> 5, lane = t & 31;
    const int ki   = blockIdx.x >> 6;
    const int rest = blockIdx.x & 63;
    const int b    = rest >> 4;
    const int l0   = (rest & 15) << 7;
    const int n0   = blockIdx.y << 7;
    const int k3   = (ki == 3) ? 1 : 0;
    const int vbase = l0 - 1 + k3;                     // x row for local m=0

    const int wm = warp >> 2, wn = warp & 3;
    const int gid = lane >> 2, tig = lane & 3;
    const int permslot = (lane & ~7) | (((lane & 3) << 1) | ((lane >> 2) & 1));

    const float* xrow0 = x + ((size_t)b * 2048 + vbase) * 512;

    // ---- load lambdas ----
    auto loadB = [&](int c, float* dst) {
        const int grp = c >> 2, typ = c & 3;
        const float* src;
        size_t rstride;
        if (typ == 0) { src = g_Mt + (((size_t)ki * 512 + n0) << 9) + (grp << 5); rstride = 512; }
        else          { src = g_PSt + (size_t)n0 * 1536 + ((typ - 1) << 9) + (grp << 5); rstride = 1536; }
        #pragma unroll
        for (int q = 0; q < 2; q++) {
            int idx = t + 512 * q;
            int n = idx >> 3, c4 = idx & 7;
            cp16(dst + n * 40 + c4 * 4, src + (size_t)n * rstride + c4 * 4);
        }
    };
    auto loadAlin = [&](int grp) {
        float* dst = sm + GL_OFF;
        const float* src = g_Xt + ((size_t)b * 2048 + vbase) * 512 + (grp << 5);
        #pragma unroll
        for (int q = 0; q < 2; q++) {
            int idx = t + 512 * q;
            int r = idx >> 3, c4 = idx & 7;
            if (vbase + r >= 0) cp16(dst + r * 40 + c4 * 4, src + (size_t)r * 512 + c4 * 4);
            else                *(float4*)(dst + r * 40 + c4 * 4) = make_float4(0.f, 0.f, 0.f, 0.f);
        }
    };
    auto issueX = [&](int grp, float* r8) {
        const float* p = xrow0 + (grp << 5) + lane;
        #pragma unroll
        for (int q = 0; q < 8; q++) {
            int m = warp + (q << 4);
            r8[q] = (vbase + m >= 0) ? __ldg(p + (size_t)m * 512) : 0.f;
        }
    };
    auto buildS = [&](int grp, int s, const float* r8, float* dst) {
        uint32_t* gu = (uint32_t*)dst;
        int j  = (grp << 5) + lane;
        int jm = (j - s) & 511;
        float wv = ws[jm];
        #pragma unroll
        for (int q = 0; q < 8; q++) {
            int m = warp + (q << 4);
            float sw = r8[q] * wv;
            float gv = sw * (1.0f / (1.0f + __expf(-sw)));
            gu[m * 40 + permslot] = f2tf32(gv);
        }
    };

    float acc[2][4][4];
    #pragma unroll
    for (int i = 0; i < 2; i++)
        #pragma unroll
        for (int jv = 0; jv < 4; jv++)
            #pragma unroll
            for (int r = 0; r < 4; r++) acc[i][jv][r] = 0.f;

    auto mmaStep = [&](const uint32_t* gu, const uint32_t* pu) {
        #pragma unroll
        for (int ks = 0; ks < 4; ks++) {
            uint32_t a[2][4];
            #pragma unroll
            for (int mi = 0; mi < 2; mi++) {
                int r = wm * 32 + mi * 16 + gid;
                uint2 lo = *(const uint2*)(gu + r * 40 + 8 * ks + 2 * tig);
                uint2 hi = *(const uint2*)(gu + (r + 8) * 40 + 8 * ks + 2 * tig);
                a[mi][0] = lo.x; a[mi][1] = hi.x; a[mi][2] = lo.y; a[mi][3] = hi.y;
            }
            #pragma unroll
            for (int nb = 0; nb < 4; nb++) {
                int cc = wn * 32 + nb * 8 + gid;
                uint2 bb = *(const uint2*)(pu + cc * 40 + 8 * ks + 2 * tig);
                mma_tf32(acc[0][nb], a[0], bb.x, bb.y);
                mma_tf32(acc[1][nb], a[1], bb.x, bb.y);
            }
        }
    };

    // ---- prologue ----
    ws[t] = W[ki * 512 + t];            // 512 threads, 512 floats
    float rA0[8], rA1[8];
    issueX(0, rA0);
    loadB(0, sm + PB_OFF);              // group: B(0) + A-lin(0)
    loadAlin(0);
    asm volatile("cp.async.commit_group;");
    loadB(1, sm + PB_OFF + TILE);       // group: B(1)
    asm volatile("cp.async.commit_group;");

    // ---- main loop: 16 groups x 4 chunk types ----
    int pb_i = 0;                       // it % 3
    #pragma unroll 1
    for (int grp = 0; grp < 16; ++grp) {
        #pragma unroll
        for (int typ = 0; typ < 4; ++typ) {
            const int it = grp * 4 + typ;

            asm volatile("cp.async.wait_group 1;");
            __syncthreads();

            // issue loads for chunk it+2
            const int c2 = it + 2;
            if (c2 < 64) {
                int pb2 = pb_i + 2; if (pb2 >= 3) pb2 -= 3;
                loadB(c2, sm + PB_OFF + pb2 * TILE);
                if ((c2 & 3) == 0) loadAlin(c2 >> 2);
            }
            asm volatile("cp.async.commit_group;");

            // register prefetch of x for next group's silu builds
            if (typ == 0 && grp + 1 < 16) {
                if (grp & 1) issueX(grp + 1, rA0);
                else         issueX(grp + 1, rA1);
            }

            // build silu A for chunk it+1 (same group, typ 1..3)
            if (typ < 3) {
                const int c1 = it + 1;
                const int s = 1 << typ;                     // (c1&3)-1 = typ
                float* gdst = sm + GS_OFF + (c1 & 1) * TILE;
                if (grp & 1) buildS(grp, s, rA1, gdst);
                else         buildS(grp, s, rA0, gdst);
            }

            // MMA on chunk it
            const uint32_t* gu = (typ == 0)
                ? (const uint32_t*)(sm + GL_OFF)
                : (const uint32_t*)(sm + GS_OFF + (it & 1) * TILE);
            const uint32_t* pu = (const uint32_t*)(sm + PB_OFF + pb_i * TILE);
            mmaStep(gu, pu);

            pb_i = (pb_i == 2) ? 0 : pb_i + 1;
        }
    }

    // ---- epilogue ----
    #pragma unroll
    for (int mi = 0; mi < 2; mi++) {
        int rloc = wm * 32 + mi * 16 + gid;
        size_t row1 = (size_t)b * 8192 + (size_t)(l0 + rloc) * 4 + ki;
        size_t row2 = row1 + 32;                            // (+8 rows) * 4
        #pragma unroll
        for (int nb = 0; nb < 4; nb++) {
            int c = n0 + wn * 32 + nb * 8 + tig * 2;
            float b0 = __ldg(bias + c);
            float b1 = __ldg(bias + c + 1);
            *(float2*)(out + row1 * 512 + c) =
                make_float2(acc[0][nb][0] + b0, acc[0][nb][1] + b1);
            *(float2*)(out + row2 * 512 + c) =
                make_float2(acc[0][nb][2] + b0, acc[0][nb][3] + b1);
        }
        // mi=1 uses acc[1]
        if (mi == 0) continue;
    }
    // second mi block written explicitly (acc index must be literal)
    {
        int rloc = wm * 32 + 16 + gid;
        size_t row1 = (size_t)b * 8192 + (size_t)(l0 + rloc) * 4 + ki;
        size_t row2 = row1 + 32;
        #pragma unroll
        for (int nb = 0; nb < 4; nb++) {
            int c = n0 + wn * 32 + nb * 8 + tig * 2;
            float b0 = __ldg(bias + c);
            float b1 = __ldg(bias + c + 1);
            *(float2*)(out + row1 * 512 + c) =
                make_float2(acc[1][nb][0] + b0, acc[1][nb][1] + b1);
            *(float2*)(out + row2 * 512 + c) =
                make_float2(acc[1][nb][2] + b0, acc[1][nb][3] + b1);
        }
    }
}

extern "C" void kernel_launch(void* const* d_in, const int* in_sizes, int n_in,
                              void* d_out, int out_size)
{
    const float* x    = (const float*)d_in[0];  // (4,1,2048,512)
    const float* W    = (const float*)d_in[1];  // (4,512)
    const float* proj = (const float*)d_in[2];  // (3072,512)
    const float* bias = (const float*)d_in[3];  // (512,)
    float* out = (float*)d_out;                 // (4,1,8192,512)

    prep_M <<<dim3(16, 16, 4), dim3(32, 8)>>>(proj, W);
    prep_PS<<<dim3(48, 16),    dim3(32, 8)>>>(proj);
    prep_X <<<4096, 256>>>(x);

    cudaFuncSetAttribute(gsu3_kernel,
                         cudaFuncAttributeMaxDynamicSharedMemorySize, SMEM_BYTES);
    dim3 grid(256, 4);
    gsu3_kernel<<<grid, THREADS, SMEM_BYTES>>>(x, W, bias, out);
}

// round 8
// speedup vs baseline: 1.5170x; 1.0612x over previous
#include <cuda_runtime.h>
#include <cstdint>

// GeometricStrideUnpool, round 5: mma.sync tf32, 256-thread CTAs (64x128 tile),
// 2 CTAs/SM. Fixed-ki CTAs, interleaved lin/s1/s2/s4 chunks, 3-stage B ring,
// build-one-ahead silu A, register-prefetched x, prep-folded tf32 operands.

#define THREADS 256
// smem layout (floats)
#define WS_OFF  0             // 512: W[ki] row
#define GL_OFF  512           // 1 x 2560: linear A tile (64 x 40)
#define GS_OFF  3072          // 2 x 2560: silu A tiles
#define PB_OFF  8192          // 3 x 5120: B tiles (128 x 40)
#define TILE_A  2560
#define TILE_B  5120
#define SMEM_FLOATS 23552
#define SMEM_BYTES  (SMEM_FLOATS * 4)

// gmem scratch written by prep kernels every launch
__device__ float g_Mt [4u * 512 * 512];    // [ki][n][k'] folded linear B, tf32, permuted
__device__ float g_PSt[512u * 1536];       // [n][si*512 + k'] silu proj B, tf32, permuted
__device__ float g_Xt [4u * 2048 * 512];   // [b][l][k'] x, tf32, permuted

__device__ __host__ __forceinline__ int kperm8(int k) {
    return (k & ~7) | (((k & 3) << 1) | ((k >> 2) & 1));   // (k,k+4) adjacent
}

__device__ __forceinline__ uint32_t f2tf32(float f) {
    uint32_t r;
    asm("cvt.rna.tf32.f32 %0, %1;" : "=r"(r) : "f"(f));
    return r;
}

__device__ __forceinline__ void cp16(void* dst, const void* src) {
    uint32_t d = (uint32_t)__cvta_generic_to_shared(dst);
    asm volatile("cp.async.cg.shared.global [%0], [%1], 16;" :: "r"(d), "l"(src));
}

__device__ __forceinline__ void mma_tf32(float* c, const uint32_t* a, uint32_t b0, uint32_t b1) {
    asm volatile(
        "mma.sync.aligned.m16n8k8.row.col.f32.tf32.tf32.f32 "
        "{%0,%1,%2,%3}, {%4,%5,%6,%7}, {%8,%9}, {%0,%1,%2,%3};"
        : "+f"(c[0]), "+f"(c[1]), "+f"(c[2]), "+f"(c[3])
        : "r"(a[0]), "r"(a[1]), "r"(a[2]), "r"(a[3]), "r"(b0), "r"(b1));
}

// ---------------- prep 1: fold linear part into M_ki, transpose+perm+tf32 ----------------
__global__ void prep_M(const float* __restrict__ proj, const float* __restrict__ W) {
    __shared__ float tile[32][33];
    const int ki = blockIdx.z;
    const int k0 = blockIdx.x * 32, n0 = blockIdx.y * 32;
    const int tx = threadIdx.x, ty = threadIdx.y;
    #pragma unroll
    for (int q = 0; q < 4; q++) {
        int kl = ty * 4 + q, k = k0 + kl, n = n0 + tx;
        float acc = 0.f;
        #pragma unroll
        for (int si = 0; si < 3; si++) {
            int s = 1 << si;
            int base = si * 1024;
            float p1 = proj[(size_t)(base + k) * 512 + n];
            float p2 = proj[(size_t)(base + ((k + s) & 511)) * 512 + n];
            float w1 = __ldg(W + ki * 512 + ((k - s) & 511));
            float w2 = __ldg(W + ki * 512 + ((k + s) & 511));
            acc += w1 * p1 - w2 * p2;
        }
        tile[kl][tx] = acc;
    }
    __syncthreads();
    #pragma unroll
    for (int q = 0; q < 4; q++) {
        int nl = ty * 4 + q, n = n0 + nl;
        int k = k0 + tx;
        ((uint32_t*)g_Mt)[(((size_t)ki * 512 + n) << 9) + kperm8(k)] = f2tf32(tile[tx][nl]);
    }
}

// ---------------- prep 2: silu proj rows, transpose+perm+tf32 ----------------
__global__ void prep_PS(const float* __restrict__ proj) {
    __shared__ float tile[32][33];
    const int k0 = blockIdx.x * 32, n0 = blockIdx.y * 32;
    const int tx = threadIdx.x, ty = threadIdx.y;
    const int srow0 = 512 + (k0 >> 9) * 1024;
    #pragma unroll
    for (int q = 0; q < 4; q++) {
        int kl = ty * 4 + q, k = k0 + kl;
        tile[kl][tx] = proj[(size_t)(srow0 + (k & 511)) * 512 + n0 + tx];
    }
    __syncthreads();
    #pragma unroll
    for (int q = 0; q < 4; q++) {
        int nl = ty * 4 + q, n = n0 + nl;
        int k = k0 + tx;
        ((uint32_t*)g_PSt)[(size_t)n * 1536 + kperm8(k)] = f2tf32(tile[tx][nl]);
    }
}

// ---------------- prep 3: x -> tf32 + permuted ----------------
__global__ void prep_X(const float* __restrict__ x) {
    size_t i = (size_t)blockIdx.x * 256 + threadIdx.x;   // float4 index, 1M total
    float4 v = ((const float4*)x)[i];
    uint32_t* dst = (uint32_t*)g_Xt + ((i >> 7) << 9);
    int k = (int)(i & 127) * 4;
    int base = k & ~7, odd = (k >> 2) & 1;
    dst[base + odd + 0] = f2tf32(v.x);
    dst[base + odd + 2] = f2tf32(v.y);
    dst[base + odd + 4] = f2tf32(v.z);
    dst[base + odd + 6] = f2tf32(v.w);
}

// ---------------- main fused kernel ----------------
__global__ void __launch_bounds__(THREADS, 2)
gsu5_kernel(const float* __restrict__ x, const float* __restrict__ W,
            const float* __restrict__ bias, float* __restrict__ out)
{
    extern __shared__ float sm[];
    float* ws = sm + WS_OFF;

    const int t = threadIdx.x, warp = t >> 5, lane = t & 31;
    const int ki = blockIdx.x >> 7;
    const int b  = (blockIdx.x >> 5) & 3;
    const int l0 = (blockIdx.x & 31) << 6;             // 64 l-rows per CTA
    const int n0 = blockIdx.y << 7;
    const int vbase = l0 - 1 + ((ki == 3) ? 1 : 0);

    const int wm = warp >> 2, wn = warp & 3;           // 2 x 4 warp grid, 32x32 tiles
    const int gid = lane >> 2, tig = lane & 3;
    const int permslot = (lane & ~7) | (((lane & 3) << 1) | ((lane >> 2) & 1));

    const float* xrow0 = x + ((size_t)b * 2048 + vbase) * 512;

    // ---- load lambdas ----
    auto loadB = [&](int c, float* dst) {              // 128n x 32k, stride 40
        const int grp = c >> 2, typ = c & 3;
        const float* src; size_t rs;
        if (typ == 0) { src = g_Mt + (((size_t)ki * 512 + n0) << 9) + (grp << 5); rs = 512; }
        else          { src = g_PSt + (size_t)n0 * 1536 + ((typ - 1) << 9) + (grp << 5); rs = 1536; }
        #pragma unroll
        for (int q = 0; q < 4; q++) {
            int idx = t + THREADS * q;                 // 0..1023
            int n = idx >> 3, c4 = idx & 7;
            cp16(dst + n * 40 + c4 * 4, src + (size_t)n * rs + c4 * 4);
        }
    };
    auto loadAlin = [&](int c) {                       // 64r x 32k, stride 40
        float* dst = sm + GL_OFF;
        const float* src = g_Xt + ((size_t)b * 2048 + vbase) * 512 + ((c >> 2) << 5);
        #pragma unroll
        for (int q = 0; q < 2; q++) {
            int idx = t + THREADS * q;                 // 0..511
            int r = idx >> 3, c4 = idx & 7;
            if (vbase + r >= 0) cp16(dst + r * 40 + c4 * 4, src + (size_t)r * 512 + c4 * 4);
            else                *(float4*)(dst + r * 40 + c4 * 4) = make_float4(0.f, 0.f, 0.f, 0.f);
        }
    };
    auto issueX = [&](int grp, float* r8) {
        const float* p = xrow0 + (grp << 5) + lane;
        #pragma unroll
        for (int q = 0; q < 8; q++) {
            int m = warp + (q << 3);                   // 0..63
            r8[q] = (vbase + m >= 0) ? __ldg(p + (size_t)m * 512) : 0.f;
        }
    };
    auto buildS = [&](int grp, int s, const float* r8, float* dst) {
        uint32_t* gu = (uint32_t*)dst;
        int j  = (grp << 5) + lane;
        int jm = (j - s) & 511;
        float wv = ws[jm];
        #pragma unroll
        for (int q = 0; q < 8; q++) {
            int m = warp + (q << 3);
            float sw = r8[q] * wv;
            float gv = sw * (1.0f / (1.0f + __expf(-sw)));
            gu[m * 40 + permslot] = f2tf32(gv);
        }
    };

    float acc[2][4][4];
    #pragma unroll
    for (int i = 0; i < 2; i++)
        #pragma unroll
        for (int jv = 0; jv < 4; jv++)
            #pragma unroll
            for (int r = 0; r < 4; r++) acc[i][jv][r] = 0.f;

    auto mmaStep = [&](const uint32_t* gu, const uint32_t* pu) {
        #pragma unroll
        for (int ks = 0; ks < 4; ks++) {
            uint32_t a[2][4];
            #pragma unroll
            for (int mi = 0; mi < 2; mi++) {
                int r = wm * 32 + mi * 16 + gid;
                uint2 lo = *(const uint2*)(gu + r * 40 + 8 * ks + 2 * tig);
                uint2 hi = *(const uint2*)(gu + (r + 8) * 40 + 8 * ks + 2 * tig);
                a[mi][0] = lo.x; a[mi][1] = hi.x; a[mi][2] = lo.y; a[mi][3] = hi.y;
            }
            #pragma unroll
            for (int nb = 0; nb < 4; nb++) {
                int cc = wn * 32 + nb * 8 + gid;
                uint2 bb = *(const uint2*)(pu + cc * 40 + 8 * ks + 2 * tig);
                mma_tf32(acc[0][nb], a[0], bb.x, bb.y);
                mma_tf32(acc[1][nb], a[1], bb.x, bb.y);
            }
        }
    };

    // ---- prologue ----
    ws[t]       = W[ki * 512 + t];
    ws[t + 256] = W[ki * 512 + t + 256];
    float rA0[8], rA1[8];
    issueX(0, rA0);
    loadB(0, sm + PB_OFF);
    loadAlin(0);
    asm volatile("cp.async.commit_group;");
    loadB(1, sm + PB_OFF + TILE_B);
    asm volatile("cp.async.commit_group;");

    // ---- main loop: 16 groups x 4 chunk types (lin, s1, s2, s4) ----
    int pb_i = 0;                       // it % 3
    #pragma unroll 1
    for (int grp = 0; grp < 16; ++grp) {
        #pragma unroll
        for (int typ = 0; typ < 4; ++typ) {
            const int it = grp * 4 + typ;

            asm volatile("cp.async.wait_group 1;");
            __syncthreads();

            // issue loads for chunk it+2
            const int c2 = it + 2;
            if (c2 < 64) {
                int pb2 = pb_i + 2; if (pb2 >= 3) pb2 -= 3;
                loadB(c2, sm + PB_OFF + pb2 * TILE_B);
                if ((c2 & 3) == 0) loadAlin(c2);
            }
            asm volatile("cp.async.commit_group;");

            // register prefetch of x for next group's silu builds
            if (typ == 0 && grp + 1 < 16) {
                if (grp & 1) issueX(grp + 1, rA0);
                else         issueX(grp + 1, rA1);
            }

            // build silu A for chunk it+1
            if (typ < 3) {
                const int c1 = it + 1;
                const int s = 1 << typ;
                float* gdst = sm + GS_OFF + (c1 & 1) * TILE_A;
                if (grp & 1) buildS(grp, s, rA1, gdst);
                else         buildS(grp, s, rA0, gdst);
            }

            // MMA on chunk it
            const uint32_t* gu = (typ == 0)
                ? (const uint32_t*)(sm + GL_OFF)
                : (const uint32_t*)(sm + GS_OFF + (it & 1) * TILE_A);
            const uint32_t* pu = (const uint32_t*)(sm + PB_OFF + pb_i * TILE_B);
            mmaStep(gu, pu);

            pb_i = (pb_i == 2) ? 0 : pb_i + 1;
        }
    }

    // ---- epilogue ----
    {
        int rloc = wm * 32 + gid;                            // mi = 0
        size_t row1 = (size_t)b * 8192 + (size_t)(l0 + rloc) * 4 + ki;
        size_t row2 = row1 + 32;                             // +8 rows
        #pragma unroll
        for (int nb = 0; nb < 4; nb++) {
            int c = n0 + wn * 32 + nb * 8 + tig * 2;
            float b0 = __ldg(bias + c);
            float b1 = __ldg(bias + c + 1);
            *(float2*)(out + row1 * 512 + c) =
                make_float2(acc[0][nb][0] + b0, acc[0][nb][1] + b1);
            *(float2*)(out + row2 * 512 + c) =
                make_float2(acc[0][nb][2] + b0, acc[0][nb][3] + b1);
        }
    }
    {
        int rloc = wm * 32 + 16 + gid;                       // mi = 1
        size_t row1 = (size_t)b * 8192 + (size_t)(l0 + rloc) * 4 + ki;
        size_t row2 = row1 + 32;
        #pragma unroll
        for (int nb = 0; nb < 4; nb++) {
            int c = n0 + wn * 32 + nb * 8 + tig * 2;
            float b0 = __ldg(bias + c);
            float b1 = __ldg(bias + c + 1);
            *(float2*)(out + row1 * 512 + c) =
                make_float2(acc[1][nb][0] + b0, acc[1][nb][1] + b1);
            *(float2*)(out + row2 * 512 + c) =
                make_float2(acc[1][nb][2] + b0, acc[1][nb][3] + b1);
        }
    }
}

extern "C" void kernel_launch(void* const* d_in, const int* in_sizes, int n_in,
                              void* d_out, int out_size)
{
    const float* x    = (const float*)d_in[0];  // (4,1,2048,512)
    const float* W    = (const float*)d_in[1];  // (4,512)
    const float* proj = (const float*)d_in[2];  // (3072,512)
    const float* bias = (const float*)d_in[3];  // (512,)
    float* out = (float*)d_out;                 // (4,1,8192,512)

    prep_M <<<dim3(16, 16, 4), dim3(32, 8)>>>(proj, W);
    prep_PS<<<dim3(48, 16),    dim3(32, 8)>>>(proj);
    prep_X <<<4096, 256>>>(x);

    cudaFuncSetAttribute(gsu5_kernel,
                         cudaFuncAttributeMaxDynamicSharedMemorySize, SMEM_BYTES);
    dim3 grid(512, 4);
    gsu5_kernel<<<grid, THREADS, SMEM_BYTES>>>(x, W, bias, out);
}

// round 9
// speedup vs baseline: 1.8746x; 1.2357x over previous
#include <cuda_runtime.h>
#include <cstdint>

// GeometricStrideUnpool, round 6: fully-precomputed operands, pure-GEMM main loop.
//  prep_M : linear part folded into per-ki 512x512 matrices (transposed, tf32, permuted)
//  prep_PS: silu proj rows (transposed, tf32, permuted)
//  prep_X : x -> tf32, permuted  (A for linear chunks)
//  prep_G : silu(x*rollW) for all (ki,s) -> tf32, permuted (A for silu chunks, 201MB)
//  main   : C[64x128] += A[64x32] @ B[128x32]^T per chunk, 64 chunks, mma.sync tf32,
//           2-stage cp.async double buffer, 3 CTAs/SM target.

#define THREADS 256
// smem layout (floats)
#define PA_OFF  0             // 2 x 2560: A tiles (64 x 40)
#define PB_OFF  5120          // 2 x 5120: B tiles (128 x 40)
#define TILE_A  2560
#define TILE_B  5120
#define SMEM_FLOATS 15360
#define SMEM_BYTES  (SMEM_FLOATS * 4)

// gmem scratch written by prep kernels every launch
__device__ float g_Mt [4u * 512 * 512];        // [ki][n][k'] folded linear B
__device__ float g_PSt[512u * 1536];           // [n][si*512 + k'] silu proj B
__device__ float g_Xt [4u * 2048 * 512];       // [b][l][k'] x (linear A)
__device__ float g_Gs [4u * 8192 * 1536];      // [ki][b*2048+l][si*512 + j'] silu A

__device__ __host__ __forceinline__ int kperm8(int k) {
    return (k & ~7) | (((k & 3) << 1) | ((k >> 2) & 1));   // (k,k+4) adjacent
}

__device__ __forceinline__ uint32_t f2tf32(float f) {
    uint32_t r;
    asm("cvt.rna.tf32.f32 %0, %1;" : "=r"(r) : "f"(f));
    return r;
}

__device__ __forceinline__ void cp16(void* dst, const void* src) {
    uint32_t d = (uint32_t)__cvta_generic_to_shared(dst);
    asm volatile("cp.async.cg.shared.global [%0], [%1], 16;" :: "r"(d), "l"(src));
}

__device__ __forceinline__ void mma_tf32(float* c, const uint32_t* a, uint32_t b0, uint32_t b1) {
    asm volatile(
        "mma.sync.aligned.m16n8k8.row.col.f32.tf32.tf32.f32 "
        "{%0,%1,%2,%3}, {%4,%5,%6,%7}, {%8,%9}, {%0,%1,%2,%3};"
        : "+f"(c[0]), "+f"(c[1]), "+f"(c[2]), "+f"(c[3])
        : "r"(a[0]), "r"(a[1]), "r"(a[2]), "r"(a[3]), "r"(b0), "r"(b1));
}

// ---------------- prep 1: fold linear part into M_ki ----------------
__global__ void prep_M(const float* __restrict__ proj, const float* __restrict__ W) {
    __shared__ float tile[32][33];
    const int ki = blockIdx.z;
    const int k0 = blockIdx.x * 32, n0 = blockIdx.y * 32;
    const int tx = threadIdx.x, ty = threadIdx.y;
    #pragma unroll
    for (int q = 0; q < 4; q++) {
        int kl = ty * 4 + q, k = k0 + kl, n = n0 + tx;
        float acc = 0.f;
        #pragma unroll
        for (int si = 0; si < 3; si++) {
            int s = 1 << si;
            int base = si * 1024;
            float p1 = proj[(size_t)(base + k) * 512 + n];
            float p2 = proj[(size_t)(base + ((k + s) & 511)) * 512 + n];
            float w1 = __ldg(W + ki * 512 + ((k - s) & 511));
            float w2 = __ldg(W + ki * 512 + ((k + s) & 511));
            acc += w1 * p1 - w2 * p2;
        }
        tile[kl][tx] = acc;
    }
    __syncthreads();
    #pragma unroll
    for (int q = 0; q < 4; q++) {
        int nl = ty * 4 + q, n = n0 + nl;
        int k = k0 + tx;
        ((uint32_t*)g_Mt)[(((size_t)ki * 512 + n) << 9) + kperm8(k)] = f2tf32(tile[tx][nl]);
    }
}

// ---------------- prep 2: silu proj rows ----------------
__global__ void prep_PS(const float* __restrict__ proj) {
    __shared__ float tile[32][33];
    const int k0 = blockIdx.x * 32, n0 = blockIdx.y * 32;
    const int tx = threadIdx.x, ty = threadIdx.y;
    const int srow0 = 512 + (k0 >> 9) * 1024;
    #pragma unroll
    for (int q = 0; q < 4; q++) {
        int kl = ty * 4 + q, k = k0 + kl;
        tile[kl][tx] = proj[(size_t)(srow0 + (k & 511)) * 512 + n0 + tx];
    }
    __syncthreads();
    #pragma unroll
    for (int q = 0; q < 4; q++) {
        int nl = ty * 4 + q, n = n0 + nl;
        int k = k0 + tx;
        ((uint32_t*)g_PSt)[(size_t)n * 1536 + kperm8(k)] = f2tf32(tile[tx][nl]);
    }
}

// ---------------- prep 3: x -> tf32 + permuted ----------------
__global__ void prep_X(const float* __restrict__ x) {
    size_t i = (size_t)blockIdx.x * 256 + threadIdx.x;   // float4 index, 1M total
    float4 v = ((const float4*)x)[i];
    uint32_t* dst = (uint32_t*)g_Xt + ((i >> 7) << 9);
    int k = (int)(i & 127) * 4;
    int base = k & ~7, odd = (k >> 2) & 1;
    dst[base + odd + 0] = f2tf32(v.x);
    dst[base + odd + 2] = f2tf32(v.y);
    dst[base + odd + 4] = f2tf32(v.z);
    dst[base + odd + 6] = f2tf32(v.w);
}

// ---------------- prep 4: silu A for all (ki, s) ----------------
__global__ void prep_G(const float* __restrict__ x, const float* __restrict__ W) {
    __shared__ float xrow[512];
    __shared__ float wsm[2048];
    const int row = blockIdx.x;                          // b*2048 + l, 8192 rows
    const int t = threadIdx.x;                           // 256
    xrow[t]       = x[(size_t)row * 512 + t];
    xrow[t + 256] = x[(size_t)row * 512 + t + 256];
    #pragma unroll
    for (int i = 0; i < 8; i++) wsm[t + 256 * i] = W[t + 256 * i];
    __syncthreads();
    #pragma unroll
    for (int ki = 0; ki < 4; ki++) {
        uint32_t* drow = (uint32_t*)g_Gs + ((size_t)ki * 8192 + row) * 1536;
        #pragma unroll
        for (int si = 0; si < 3; si++) {
            int s = 1 << si;
            #pragma unroll
            for (int jj = 0; jj < 2; jj++) {
                int j = t + 256 * jj;
                float sw = xrow[j] * wsm[ki * 512 + ((j - s) & 511)];
                float gv = sw * (1.0f / (1.0f + __expf(-sw)));
                drow[si * 512 + kperm8(j)] = f2tf32(gv);
            }
        }
    }
}

// ---------------- main GEMM kernel ----------------
__global__ void __launch_bounds__(THREADS, 3)
gsu6_kernel(const float* __restrict__ bias, float* __restrict__ out)
{
    extern __shared__ float sm[];

    const int t = threadIdx.x, warp = t >> 5, lane = t & 31;
    // n-tile fastest so A-sharing CTAs are co-resident
    const int nt   = blockIdx.x & 3;
    const int lt   = (blockIdx.x >> 2) & 31;
    const int b    = (blockIdx.x >> 7) & 3;
    const int ki   = blockIdx.x >> 9;
    const int l0   = lt << 6;
    const int n0   = nt << 7;
    const int vbase = l0 - 1 + ((ki == 3) ? 1 : 0);

    const int wm = warp >> 2, wn = warp & 3;             // 2 x 4 warp grid
    const int gid = lane >> 2, tig = lane & 3;

    // ---- load lambdas ----
    auto loadB = [&](int c, float* dst) {                // 128n x 32k, stride 40
        const int grp = c >> 2, typ = c & 3;
        const float* src; size_t rs;
        if (typ == 0) { src = g_Mt + (((size_t)ki * 512 + n0) << 9) + (grp << 5); rs = 512; }
        else          { src = g_PSt + (size_t)n0 * 1536 + ((typ - 1) << 9) + (grp << 5); rs = 1536; }
        #pragma unroll
        for (int q = 0; q < 4; q++) {
            int idx = t + THREADS * q;                   // 0..1023
            int n = idx >> 3, c4 = idx & 7;
            cp16(dst + n * 40 + c4 * 4, src + (size_t)n * rs + c4 * 4);
        }
    };
    auto loadA = [&](int c, float* dst) {                // 64r x 32k, stride 40
        const int grp = c >> 2, typ = c & 3;
        const float* src; size_t rs;
        if (typ == 0) { src = g_Xt + ((size_t)b * 2048 + vbase) * 512 + (grp << 5); rs = 512; }
        else {
            src = g_Gs + ((size_t)ki * 8192 + b * 2048 + vbase) * 1536
                       + ((typ - 1) << 9) + (grp << 5);
            rs = 1536;
        }
        #pragma unroll
        for (int q = 0; q < 2; q++) {
            int idx = t + THREADS * q;                   // 0..511
            int r = idx >> 3, c4 = idx & 7;
            if (vbase + r >= 0) cp16(dst + r * 40 + c4 * 4, src + (size_t)r * rs + c4 * 4);
            else                *(float4*)(dst + r * 40 + c4 * 4) = make_float4(0.f, 0.f, 0.f, 0.f);
        }
    };

    float acc[2][4][4];
    #pragma unroll
    for (int i = 0; i < 2; i++)
        #pragma unroll
        for (int jv = 0; jv < 4; jv++)
            #pragma unroll
            for (int r = 0; r < 4; r++) acc[i][jv][r] = 0.f;

    auto mmaStep = [&](const uint32_t* gu, const uint32_t* pu) {
        #pragma unroll
        for (int ks = 0; ks < 4; ks++) {
            uint32_t a[2][4];
            #pragma unroll
            for (int mi = 0; mi < 2; mi++) {
                int r = wm * 32 + mi * 16 + gid;
                uint2 lo = *(const uint2*)(gu + r * 40 + 8 * ks + 2 * tig);
                uint2 hi = *(const uint2*)(gu + (r + 8) * 40 + 8 * ks + 2 * tig);
                a[mi][0] = lo.x; a[mi][1] = hi.x; a[mi][2] = lo.y; a[mi][3] = hi.y;
            }
            #pragma unroll
            for (int nb = 0; nb < 4; nb++) {
                int cc = wn * 32 + nb * 8 + gid;
                uint2 bb = *(const uint2*)(pu + cc * 40 + 8 * ks + 2 * tig);
                mma_tf32(acc[0][nb], a[0], bb.x, bb.y);
                mma_tf32(acc[1][nb], a[1], bb.x, bb.y);
            }
        }
    };

    // ---- prologue: chunk 0 ----
    loadB(0, sm + PB_OFF);
    loadA(0, sm + PA_OFF);
    asm volatile("cp.async.commit_group;");

    // ---- main loop: 64 chunks, 2-stage double buffer ----
    #pragma unroll 1
    for (int it = 0; it < 64; ++it) {
        const int cur = it & 1, nxt = cur ^ 1;

        asm volatile("cp.async.wait_group 0;");
        __syncthreads();

        if (it + 1 < 64) {
            loadB(it + 1, sm + PB_OFF + nxt * TILE_B);
            loadA(it + 1, sm + PA_OFF + nxt * TILE_A);
        }
        asm volatile("cp.async.commit_group;");

        mmaStep((const uint32_t*)(sm + PA_OFF + cur * TILE_A),
                (const uint32_t*)(sm + PB_OFF + cur * TILE_B));
    }

    // ---- epilogue ----
    {
        int rloc = wm * 32 + gid;                            // mi = 0
        size_t row1 = (size_t)b * 8192 + (size_t)(l0 + rloc) * 4 + ki;
        size_t row2 = row1 + 32;                             // +8 rows
        #pragma unroll
        for (int nb = 0; nb < 4; nb++) {
            int c = n0 + wn * 32 + nb * 8 + tig * 2;
            float b0 = __ldg(bias + c);
            float b1 = __ldg(bias + c + 1);
            *(float2*)(out + row1 * 512 + c) =
                make_float2(acc[0][nb][0] + b0, acc[0][nb][1] + b1);
            *(float2*)(out + row2 * 512 + c) =
                make_float2(acc[0][nb][2] + b0, acc[0][nb][3] + b1);
        }
    }
    {
        int rloc = wm * 32 + 16 + gid;                       // mi = 1
        size_t row1 = (size_t)b * 8192 + (size_t)(l0 + rloc) * 4 + ki;
        size_t row2 = row1 + 32;
        #pragma unroll
        for (int nb = 0; nb < 4; nb++) {
            int c = n0 + wn * 32 + nb * 8 + tig * 2;
            float b0 = __ldg(bias + c);
            float b1 = __ldg(bias + c + 1);
            *(float2*)(out + row1 * 512 + c) =
                make_float2(acc[1][nb][0] + b0, acc[1][nb][1] + b1);
            *(float2*)(out + row2 * 512 + c) =
                make_float2(acc[1][nb][2] + b0, acc[1][nb][3] + b1);
        }
    }
}

extern "C" void kernel_launch(void* const* d_in, const int* in_sizes, int n_in,
                              void* d_out, int out_size)
{
    const float* x    = (const float*)d_in[0];  // (4,1,2048,512)
    const float* W    = (const float*)d_in[1];  // (4,512)
    const float* proj = (const float*)d_in[2];  // (3072,512)
    const float* bias = (const float*)d_in[3];  // (512,)
    float* out = (float*)d_out;                 // (4,1,8192,512)

    prep_M <<<dim3(16, 16, 4), dim3(32, 8)>>>(proj, W);
    prep_PS<<<dim3(48, 16),    dim3(32, 8)>>>(proj);
    prep_X <<<4096, 256>>>(x);
    prep_G <<<8192, 256>>>(x, W);

    cudaFuncSetAttribute(gsu6_kernel,
                         cudaFuncAttributeMaxDynamicSharedMemorySize, SMEM_BYTES);
    gsu6_kernel<<<2048, THREADS, SMEM_BYTES>>>(bias, out);
}

// round 10
// speedup vs baseline: 2.0511x; 1.0941x over previous
#include <cuda_runtime.h>
#include <cstdint>

// GeometricStrideUnpool, round 7: pure-GEMM main loop with ldmatrix fragment
// loads (tf32 tiles read as b16 8x8 matrices), plain stride-36 smem tiles,
// unpermuted prep layouts, 2-stage cp.async, 3 CTAs/SM.

#define THREADS 256
// smem layout (floats)
#define PA_OFF  0             // 2 x 2304: A tiles (64 x 36)
#define PB_OFF  4608          // 2 x 4608: B tiles (128 x 36)
#define TILE_A  2304
#define TILE_B  4608
#define SMEM_FLOATS 13824
#define SMEM_BYTES  (SMEM_FLOATS * 4)

// gmem scratch written by prep kernels every launch
__device__ float g_Mt [4u * 512 * 512];        // [ki][n][k] folded linear B, tf32
__device__ float g_PSt[512u * 1536];           // [n][si*512 + k] silu proj B, tf32
__device__ float g_Xt [4u * 2048 * 512];       // [b][l][k] x, tf32 (linear A)
__device__ float g_Gs [4u * 8192 * 1536];      // [ki][b*2048+l][si*512 + j] silu A, tf32

__device__ __forceinline__ uint32_t f2tf32(float f) {
    uint32_t r;
    asm("cvt.rna.tf32.f32 %0, %1;" : "=r"(r) : "f"(f));
    return r;
}

__device__ __forceinline__ void cp16(void* dst, const void* src) {
    uint32_t d = (uint32_t)__cvta_generic_to_shared(dst);
    asm volatile("cp.async.cg.shared.global [%0], [%1], 16;" :: "r"(d), "l"(src));
}

__device__ __forceinline__ void ldsm4(uint32_t* r, uint32_t addr) {
    asm volatile("ldmatrix.sync.aligned.m8n8.x4.shared.b16 {%0,%1,%2,%3}, [%4];"
                 : "=r"(r[0]), "=r"(r[1]), "=r"(r[2]), "=r"(r[3]) : "r"(addr));
}

__device__ __forceinline__ void mma_tf32(float* c, const uint32_t* a, uint32_t b0, uint32_t b1) {
    asm volatile(
        "mma.sync.aligned.m16n8k8.row.col.f32.tf32.tf32.f32 "
        "{%0,%1,%2,%3}, {%4,%5,%6,%7}, {%8,%9}, {%0,%1,%2,%3};"
        : "+f"(c[0]), "+f"(c[1]), "+f"(c[2]), "+f"(c[3])
        : "r"(a[0]), "r"(a[1]), "r"(a[2]), "r"(a[3]), "r"(b0), "r"(b1));
}

// ---------------- prep 1: fold linear part into M_ki (transposed tf32) ----------------
__global__ void prep_M(const float* __restrict__ proj, const float* __restrict__ W) {
    __shared__ float tile[32][33];
    const int ki = blockIdx.z;
    const int k0 = blockIdx.x * 32, n0 = blockIdx.y * 32;
    const int tx = threadIdx.x, ty = threadIdx.y;
    #pragma unroll
    for (int q = 0; q < 4; q++) {
        int kl = ty * 4 + q, k = k0 + kl, n = n0 + tx;
        float acc = 0.f;
        #pragma unroll
        for (int si = 0; si < 3; si++) {
            int s = 1 << si;
            int base = si * 1024;
            float p1 = proj[(size_t)(base + k) * 512 + n];
            float p2 = proj[(size_t)(base + ((k + s) & 511)) * 512 + n];
            float w1 = __ldg(W + ki * 512 + ((k - s) & 511));
            float w2 = __ldg(W + ki * 512 + ((k + s) & 511));
            acc += w1 * p1 - w2 * p2;
        }
        tile[kl][tx] = acc;
    }
    __syncthreads();
    #pragma unroll
    for (int q = 0; q < 4; q++) {
        int nl = ty * 4 + q, n = n0 + nl;
        ((uint32_t*)g_Mt)[(((size_t)ki * 512 + n) << 9) + k0 + tx] = f2tf32(tile[tx][nl]);
    }
}

// ---------------- prep 2: silu proj rows (transposed tf32) ----------------
__global__ void prep_PS(const float* __restrict__ proj) {
    __shared__ float tile[32][33];
    const int k0 = blockIdx.x * 32, n0 = blockIdx.y * 32;
    const int tx = threadIdx.x, ty = threadIdx.y;
    const int srow0 = 512 + (k0 >> 9) * 1024;
    #pragma unroll
    for (int q = 0; q < 4; q++) {
        int kl = ty * 4 + q, k = k0 + kl;
        tile[kl][tx] = proj[(size_t)(srow0 + (k & 511)) * 512 + n0 + tx];
    }
    __syncthreads();
    #pragma unroll
    for (int q = 0; q < 4; q++) {
        int nl = ty * 4 + q, n = n0 + nl;
        ((uint32_t*)g_PSt)[(size_t)n * 1536 + k0 + tx] = f2tf32(tile[tx][nl]);
    }
}

// ---------------- prep 3: x -> tf32 ----------------
__global__ void prep_X(const float* __restrict__ x) {
    size_t i = (size_t)blockIdx.x * 256 + threadIdx.x;   // float4 index, 1M total
    float4 v = ((const float4*)x)[i];
    uint32_t* dst = (uint32_t*)g_Xt + i * 4;
    dst[0] = f2tf32(v.x); dst[1] = f2tf32(v.y);
    dst[2] = f2tf32(v.z); dst[3] = f2tf32(v.w);
}

// ---------------- prep 4: silu A for all (ki, s), tf32 ----------------
__global__ void prep_G(const float* __restrict__ x, const float* __restrict__ W) {
    __shared__ float xrow[512];
    __shared__ float wsm[2048];
    const int row = blockIdx.x;                          // b*2048 + l, 8192 rows
    const int t = threadIdx.x;                           // 256
    xrow[t]       = x[(size_t)row * 512 + t];
    xrow[t + 256] = x[(size_t)row * 512 + t + 256];
    #pragma unroll
    for (int i = 0; i < 8; i++) wsm[t + 256 * i] = W[t + 256 * i];
    __syncthreads();
    #pragma unroll
    for (int ki = 0; ki < 4; ki++) {
        uint32_t* drow = (uint32_t*)g_Gs + ((size_t)ki * 8192 + row) * 1536;
        #pragma unroll
        for (int si = 0; si < 3; si++) {
            int s = 1 << si;
            #pragma unroll
            for (int jj = 0; jj < 2; jj++) {
                int j = t + 256 * jj;
                float sw = xrow[j] * wsm[ki * 512 + ((j - s) & 511)];
                float gv = sw * (1.0f / (1.0f + __expf(-sw)));
                drow[si * 512 + j] = f2tf32(gv);
            }
        }
    }
}

// ---------------- main GEMM kernel ----------------
__global__ void __launch_bounds__(THREADS, 3)
gsu7_kernel(const float* __restrict__ bias, float* __restrict__ out)
{
    extern __shared__ float sm[];

    const int t = threadIdx.x, warp = t >> 5, lane = t & 31;
    // n-tile fastest so A-sharing CTAs are co-resident
    const int nt   = blockIdx.x & 3;
    const int lt   = (blockIdx.x >> 2) & 31;
    const int b    = (blockIdx.x >> 7) & 3;
    const int ki   = blockIdx.x >> 9;
    const int l0   = lt << 6;
    const int n0   = nt << 7;
    const int vbase = l0 - 1 + ((ki == 3) ? 1 : 0);

    const int wm = warp >> 2, wn = warp & 3;             // 2 x 4 warp grid, 32x32 tiles
    const int gid = lane >> 2, tig = lane & 3;

    // ---- ldmatrix lane addresses (byte offsets within a tile) ----
    const int lgrp = lane >> 3, lr = lane & 7;
    uint32_t aoff[2], boff[2];
    #pragma unroll
    for (int mi = 0; mi < 2; mi++) {
        int row = wm * 32 + mi * 16 + (lgrp & 1) * 8 + lr;
        aoff[mi] = (uint32_t)((row * 36 + (lgrp >> 1) * 4) * 4);
    }
    #pragma unroll
    for (int p = 0; p < 2; p++) {
        int row = wn * 32 + p * 16 + (lgrp >> 1) * 8 + lr;
        boff[p] = (uint32_t)((row * 36 + (lgrp & 1) * 4) * 4);
    }
    uint32_t smb;
    {
        uint64_t a64 = __cvta_generic_to_shared(sm);
        smb = (uint32_t)a64;
    }

    // ---- load lambdas ----
    auto loadB = [&](int c, float* dst) {                // 128n x 32k, stride 36
        const int grp = c >> 2, typ = c & 3;
        const float* src; size_t rs;
        if (typ == 0) { src = g_Mt + (((size_t)ki * 512 + n0) << 9) + (grp << 5); rs = 512; }
        else          { src = g_PSt + (size_t)n0 * 1536 + ((typ - 1) << 9) + (grp << 5); rs = 1536; }
        #pragma unroll
        for (int q = 0; q < 4; q++) {
            int idx = t + THREADS * q;                   // 0..1023
            int n = idx >> 3, c4 = idx & 7;
            cp16(dst + n * 36 + c4 * 4, src + (size_t)n * rs + c4 * 4);
        }
    };
    auto loadA = [&](int c, float* dst) {                // 64r x 32k, stride 36
        const int grp = c >> 2, typ = c & 3;
        const float* src; size_t rs;
        if (typ == 0) { src = g_Xt + ((size_t)b * 2048 + vbase) * 512 + (grp << 5); rs = 512; }
        else {
            src = g_Gs + ((size_t)ki * 8192 + b * 2048 + vbase) * 1536
                       + ((typ - 1) << 9) + (grp << 5);
            rs = 1536;
        }
        #pragma unroll
        for (int q = 0; q < 2; q++) {
            int idx = t + THREADS * q;                   // 0..511
            int r = idx >> 3, c4 = idx & 7;
            if (vbase + r >= 0) cp16(dst + r * 36 + c4 * 4, src + (size_t)r * rs + c4 * 4);
            else                *(float4*)(dst + r * 36 + c4 * 4) = make_float4(0.f, 0.f, 0.f, 0.f);
        }
    };

    float acc[2][4][4];
    #pragma unroll
    for (int i = 0; i < 2; i++)
        #pragma unroll
        for (int jv = 0; jv < 4; jv++)
            #pragma unroll
            for (int r = 0; r < 4; r++) acc[i][jv][r] = 0.f;

    auto mmaStep = [&](uint32_t aBase, uint32_t bBase) {
        #pragma unroll
        for (int ks = 0; ks < 4; ks++) {
            uint32_t a0[4], a1[4], p0[4], p1[4];
            ldsm4(a0, aBase + aoff[0] + ks * 32);
            ldsm4(a1, aBase + aoff[1] + ks * 32);
            ldsm4(p0, bBase + boff[0] + ks * 32);
            ldsm4(p1, bBase + boff[1] + ks * 32);
            mma_tf32(acc[0][0], a0, p0[0], p0[1]);
            mma_tf32(acc[0][1], a0, p0[2], p0[3]);
            mma_tf32(acc[0][2], a0, p1[0], p1[1]);
            mma_tf32(acc[0][3], a0, p1[2], p1[3]);
            mma_tf32(acc[1][0], a1, p0[0], p0[1]);
            mma_tf32(acc[1][1], a1, p0[2], p0[3]);
            mma_tf32(acc[1][2], a1, p1[0], p1[1]);
            mma_tf32(acc[1][3], a1, p1[2], p1[3]);
        }
    };

    // ---- prologue: chunk 0 ----
    loadB(0, sm + PB_OFF);
    loadA(0, sm + PA_OFF);
    asm volatile("cp.async.commit_group;");

    // ---- main loop: 64 chunks, 2-stage double buffer ----
    #pragma unroll 1
    for (int it = 0; it < 64; ++it) {
        const int cur = it & 1, nxt = cur ^ 1;

        asm volatile("cp.async.wait_group 0;");
        __syncthreads();

        if (it + 1 < 64) {
            loadB(it + 1, sm + PB_OFF + nxt * TILE_B);
            loadA(it + 1, sm + PA_OFF + nxt * TILE_A);
        }
        asm volatile("cp.async.commit_group;");

        mmaStep(smb + (PA_OFF + cur * TILE_A) * 4,
                smb + (PB_OFF + cur * TILE_B) * 4);
    }

    // ---- epilogue ----
    {
        int rloc = wm * 32 + gid;                            // mi = 0
        size_t row1 = (size_t)b * 8192 + (size_t)(l0 + rloc) * 4 + ki;
        size_t row2 = row1 + 32;                             // +8 rows
        #pragma unroll
        for (int nb = 0; nb < 4; nb++) {
            int c = n0 + wn * 32 + nb * 8 + tig * 2;
            float b0 = __ldg(bias + c);
            float b1 = __ldg(bias + c + 1);
            *(float2*)(out + row1 * 512 + c) =
                make_float2(acc[0][nb][0] + b0, acc[0][nb][1] + b1);
            *(float2*)(out + row2 * 512 + c) =
                make_float2(acc[0][nb][2] + b0, acc[0][nb][3] + b1);
        }
    }
    {
        int rloc = wm * 32 + 16 + gid;                       // mi = 1
        size_t row1 = (size_t)b * 8192 + (size_t)(l0 + rloc) * 4 + ki;
        size_t row2 = row1 + 32;
        #pragma unroll
        for (int nb = 0; nb < 4; nb++) {
            int c = n0 + wn * 32 + nb * 8 + tig * 2;
            float b0 = __ldg(bias + c);
            float b1 = __ldg(bias + c + 1);
            *(float2*)(out + row1 * 512 + c) =
                make_float2(acc[1][nb][0] + b0, acc[1][nb][1] + b1);
            *(float2*)(out + row2 * 512 + c) =
                make_float2(acc[1][nb][2] + b0, acc[1][nb][3] + b1);
        }
    }
}

extern "C" void kernel_launch(void* const* d_in, const int* in_sizes, int n_in,
                              void* d_out, int out_size)
{
    const float* x    = (const float*)d_in[0];  // (4,1,2048,512)
    const float* W    = (const float*)d_in[1];  // (4,512)
    const float* proj = (const float*)d_in[2];  // (3072,512)
    const float* bias = (const float*)d_in[3];  // (512,)
    float* out = (float*)d_out;                 // (4,1,8192,512)

    prep_M <<<dim3(16, 16, 4), dim3(32, 8)>>>(proj, W);
    prep_PS<<<dim3(48, 16),    dim3(32, 8)>>>(proj);
    prep_X <<<4096, 256>>>(x);
    prep_G <<<8192, 256>>>(x, W);

    cudaFuncSetAttribute(gsu7_kernel,
                         cudaFuncAttributeMaxDynamicSharedMemorySize, SMEM_BYTES);
    gsu7_kernel<<<2048, THREADS, SMEM_BYTES>>>(bias, out);
}